// round 13
// baseline (speedup 1.0000x reference)
#include <cuda_runtime.h>
#include <cuda_fp16.h>
#include <cstdint>

#define BSZ   512
#define TLEN  128
#define ISZ   256
#define HSZ   256
#define NCLS  100
#define NSTEP 26
#define XDIM  512
#define GDIM  1024
#define WIH_LD 356
#define BLANK_ID 3
#define RPB   4
#define NBLK  128
#define GRPBLK 32
#define NTHR  512
#define XSTR  528            // gates smem slab row stride (bytes), 16-aligned
#define PHSTR 272            // projH smem row stride (bytes), 16-aligned
#define WISTR 264            // Wi2h staging stride (bytes), 8-aligned ONLY
#define CSTR  136            // context-combine row stride (half2), bank-safe
#define TAIL_BYTES (2048 + 2048 + 512 + 1024 + 2048 + 2048)
#define SMEM_BYTES (512 * PHSTR + 2 * 64 * XSTR + TAIL_BYTES)   // 216576

// ------------------------- device scratch -----------------------------------
__device__ uint8_t g_batchH_f8[BSZ * TLEN * ISZ];
__device__ uint8_t g_X_f8[BSZ * XDIM];
__device__ float  g_gates[BSZ * GDIM];
__device__ float  g_c[BSZ * HSZ];
__device__ uint8_t g_hs_f8[BSZ * NSTEP * HSZ];
__device__ uint8_t g_Wcat_f8[GDIM * XDIM];     // x16 scaled
__device__ uint8_t g_Wi2h_f8[HSZ * ISZ];       // x16 scaled
__device__ uint8_t g_Wgen_f8[NCLS * HSZ];      // x16 scaled
__device__ __half g_Wh2hT_h[HSZ * HSZ];
__device__ float  g_Wemb[NCLS * GDIM];
__device__ unsigned g_count[4 * 32];
__device__ volatile unsigned g_epoch[4 * 32];

// ------------------------- fast math ----------------------------------------
__device__ __forceinline__ float tanh_fast(float x) {
    float y;
    asm("tanh.approx.f32 %0, %1;" : "=f"(y) : "f"(x));
    return y;
}
__device__ __forceinline__ float fast_sigmoid(float x) {
    return 0.5f * (1.0f + tanh_fast(0.5f * x));
}
__device__ __forceinline__ __half2 tanh2(__half2 x) {
    uint32_t xi = *(uint32_t*)&x, yo;
    asm("tanh.approx.f16x2 %0, %1;" : "=r"(yo) : "r"(xi));
    return *(__half2*)&yo;
}
__device__ __forceinline__ uint16_t h2_to_e4m3x2(__half2 h) {
    uint16_t r;
    asm("cvt.rn.satfinite.e4m3x2.f16x2 %0, %1;" : "=h"(r) : "r"(*(uint32_t*)&h));
    return r;
}
__device__ __forceinline__ __half2 e4m3x2_to_h2(uint16_t b) {
    uint32_t r;
    asm("cvt.rn.f16x2.e4m3x2 %0, %1;" : "=r"(r) : "h"(b));
    return *(__half2*)&r;
}
__device__ __forceinline__ uint8_t f32_to_e4m3(float v) {
    return (uint8_t)h2_to_e4m3x2(__floats2half2_rn(v, v));
}
__device__ __forceinline__ uint32_t pack_e4m3x4(float a, float b, float c, float d) {
    return (uint32_t)h2_to_e4m3x2(__floats2half2_rn(a, b)) |
           ((uint32_t)h2_to_e4m3x2(__floats2half2_rn(c, d)) << 16);
}
#define MMA_E4M3(acc, a0, a1, a2, a3, b0, b1)                                  \
    asm volatile(                                                              \
        "mma.sync.aligned.m16n8k32.row.col.f32.e4m3.e4m3.f32 "                 \
        "{%0,%1,%2,%3}, {%4,%5,%6,%7}, {%8,%9}, {%0,%1,%2,%3};"                \
        : "+f"(acc[0]), "+f"(acc[1]), "+f"(acc[2]), "+f"(acc[3])               \
        : "r"(a0), "r"(a1), "r"(a2), "r"(a3), "r"(b0), "r"(b1))

// named barrier for one 128-thread row group (ids 1..4; 0 = __syncthreads)
__device__ __forceinline__ void bar_group(int rg) {
    asm volatile("bar.sync %0, %1;" :: "r"(rg + 1), "r"(128) : "memory");
}

// ------------------------- group barrier (32 blocks) -------------------------
__device__ __forceinline__ void group_sync(int g) {
    __syncthreads();
    if (threadIdx.x == 0) {
        const int slot = g * 32;
        unsigned my = g_epoch[slot];
        __threadfence();
        unsigned old = atomicAdd(&g_count[slot], 1u);
        if (old == GRPBLK - 1) {
            g_count[slot] = 0;
            __threadfence();
            g_epoch[slot] = my + 1;
        } else {
            while (g_epoch[slot] == my) { __nanosleep(16); }
            __threadfence();
        }
    }
    __syncthreads();
}

// ------------------------- init ----------------------------------------------
__global__ void init_kernel(const float* __restrict__ W_ih,
                            const float* __restrict__ W_hh,
                            const float* __restrict__ b_ih,
                            const float* __restrict__ b_hh,
                            const float* __restrict__ W_i2h,
                            const float* __restrict__ W_h2h,
                            const float* __restrict__ W_gen) {
    int idx = blockIdx.x * 256 + threadIdx.x;
    if (idx < GDIM * XDIM) {
        int j = idx >> 9, k = idx & 511;
        float v = (k < 256) ? W_ih[j * WIH_LD + k] : W_hh[j * 256 + (k - 256)];
        g_Wcat_f8[idx] = f32_to_e4m3(v * 16.0f);
    }
    if (idx < HSZ * HSZ) {
        int j = idx >> 8, k = idx & 255;
        g_Wh2hT_h[k * HSZ + j] = __float2half_rn(W_h2h[idx]);
        g_Wi2h_f8[idx] = f32_to_e4m3(W_i2h[idx] * 16.0f);
    }
    if (idx < NCLS * HSZ) g_Wgen_f8[idx] = f32_to_e4m3(W_gen[idx] * 16.0f);
    if (idx < NCLS * GDIM) {
        int cls = idx >> 10, c = idx & 1023;
        g_Wemb[idx] = W_ih[(size_t)c * WIH_LD + 256 + cls] + b_ih[c] + b_hh[c];
    }
    if (idx < BSZ * HSZ) g_c[idx] = 0.0f;
}

// ------------------------- e4m3 MMA GEMM (logits), tile 128x64 ---------------
__global__ __launch_bounds__(256) void qgemm_logits(
    const uint8_t* __restrict__ Aptr, const uint8_t* __restrict__ Bw,
    float* __restrict__ Cm,
    int M, int N, int K, int lda, int ldb, int ldc,
    const float* __restrict__ bias) {

    __shared__ uint8_t As[128 * 80];
    __shared__ uint8_t Bs[64 * 80];

    const int m0 = blockIdx.y * 128, n0 = blockIdx.x * 64;
    const int tid = threadIdx.x, lane = tid & 31, warp = tid >> 5;
    const int wm = (warp >> 1) * 32, wn = (warp & 1) * 32;
    const int gID = lane >> 2, tig = lane & 3;
    const int ar = tid >> 1, aoff = (tid & 1) << 5;
    const int br = tid >> 2, boff = (tid & 3) << 4;

    float acc[2][4][4];
#pragma unroll
    for (int mf = 0; mf < 2; mf++)
#pragma unroll
        for (int i = 0; i < 4; i++)
#pragma unroll
            for (int j = 0; j < 4; j++) acc[mf][i][j] = 0.0f;

    auto loadA = [&](int k0, uint4& o0, uint4& o1) {
        const uint8_t* p = Aptr + (size_t)(m0 + ar) * lda + k0 + aoff;
        o0 = *(const uint4*)p;
        o1 = *(const uint4*)(p + 16);
    };
    auto loadB = [&](int k0) -> uint4 {
        if (n0 + br < N)
            return *(const uint4*)(Bw + (size_t)(n0 + br) * ldb + k0 + boff);
        return make_uint4(0u, 0u, 0u, 0u);
    };

    uint4 a0R, a1R, bR;
    loadA(0, a0R, a1R);
    bR = loadB(0);
    const int iters = K >> 6;

    for (int it = 0; it < iters; it++) {
        __syncthreads();
        *(uint4*)&As[ar * 80 + aoff] = a0R;
        *(uint4*)&As[ar * 80 + aoff + 16] = a1R;
        *(uint4*)&Bs[br * 80 + boff] = bR;
        __syncthreads();
        if (it + 1 < iters) {
            loadA((it + 1) << 6, a0R, a1R);
            bR = loadB((it + 1) << 6);
        }
#pragma unroll
        for (int kk = 0; kk < 64; kk += 32) {
            uint32_t af[2][4];
#pragma unroll
            for (int mf = 0; mf < 2; mf++) {
                int rb = wm + mf * 16 + gID;
                af[mf][0] = *(uint32_t*)&As[rb * 80 + kk + tig * 4];
                af[mf][1] = *(uint32_t*)&As[(rb + 8) * 80 + kk + tig * 4];
                af[mf][2] = *(uint32_t*)&As[rb * 80 + kk + 16 + tig * 4];
                af[mf][3] = *(uint32_t*)&As[(rb + 8) * 80 + kk + 16 + tig * 4];
            }
#pragma unroll
            for (int nt = 0; nt < 4; nt++) {
                uint32_t b0 = *(uint32_t*)&Bs[(wn + nt * 8 + gID) * 80 + kk + tig * 4];
                uint32_t b1 = *(uint32_t*)&Bs[(wn + nt * 8 + gID) * 80 + kk + 16 + tig * 4];
#pragma unroll
                for (int mf = 0; mf < 2; mf++)
                    MMA_E4M3(acc[mf][nt], af[mf][0], af[mf][1], af[mf][2],
                             af[mf][3], b0, b1);
            }
        }
    }

    const float sc = 1.0f / 16.0f;
#pragma unroll
    for (int mf = 0; mf < 2; mf++) {
        const int r0 = m0 + wm + mf * 16 + gID, r1 = r0 + 8;
#pragma unroll
        for (int nt = 0; nt < 4; nt++) {
            int cb = n0 + wn + nt * 8 + 2 * tig;
#pragma unroll
            for (int hr = 0; hr < 2; hr++) {
                int r = hr ? r1 : r0;
                if (r >= M || cb >= N) continue;
                float v0 = acc[mf][nt][hr * 2 + 0] * sc + bias[cb];
                float v1 = acc[mf][nt][hr * 2 + 1] * sc + bias[cb + 1];
                if (cb == BLANK_ID) v0 = -10000.0f;
                if (cb + 1 == BLANK_ID) v1 = -10000.0f;
                *(float2*)(Cm + (size_t)r * ldc + cb) = make_float2(v0, v1);
            }
        }
    }
}

// ------------------------- persistent kernel: prolog + 26 steps --------------
__global__ __launch_bounds__(NTHR, 1) void persistent_steps(
    const float* __restrict__ batch_H, const int* __restrict__ text,
    const float* __restrict__ b_h2h, const float* __restrict__ wscore) {

    extern __shared__ char dyn[];
    uint8_t* sPH = (uint8_t*)dyn;                       // [512][PHSTR]
    uint8_t* Bs8 = sPH + 512 * PHSTR;                   // [64][XSTR]
    uint8_t* As8 = Bs8 + 64 * XSTR;                     // [64][XSTR]
    __half2* redh = (__half2*)As8;                      // overlay (phase A)
    char* tail = (char*)(As8 + 64 * XSTR);
    __half*  sh   = (__half*)tail;                      // [4][256]
    __half*  sp_h = sh + 1024;                          // [4][256]
    __half*  sw_h = sp_h + 1024;                        // [256]
    float*   sb   = (float*)(sw_h + 256);               // [256]
    float*   se   = sb + 256;                           // [4][128]
    __half2* seh  = (__half2*)(se + 512);               // [4][128]

    const int tid = threadIdx.x, lane = tid & 31, warp = tid >> 5;
    const int bid = blockIdx.x;
    const int grp = bid >> 5;
    const int lid = bid & 31;
    const int b0 = bid * RPB;
    const int m0 = grp * 128 + (lid >> 4) * 64;
    const int n0 = (lid & 15) * 64;
    const int wm4 = (warp >> 2) * 16, wn4 = (warp & 3) * 16;
    const int gID = lane >> 2, tig = lane & 3;
    const int rg = tid >> 7;              // row group 0..3
    const int gtid = tid & 127;           // tid within group
    const int gwarp = (warp & 3);         // warp within group

    if (tid < 256) {
        sw_h[tid] = __float2half_rn(wscore[tid]);
        sb[tid] = b_h2h[tid];
    }

    // ========== PROLOG: projH slice -> sPH, batch_H -> g_batchH_f8 ==========
    {
        uint8_t* WB = Bs8;
#pragma unroll
        for (int i = 0; i < 8; i++) {
            int linear = tid + (i << 9);
            int row = linear >> 4, c = (linear & 15) << 4;
            uint4 v = *(const uint4*)(g_Wi2h_f8 + row * 256 + c);
            *(uint2*)&WB[row * WISTR + c] = make_uint2(v.x, v.y);
            *(uint2*)&WB[row * WISTR + c + 8] = make_uint2(v.z, v.w);
        }
        __syncthreads();

        const float* Abase = batch_H + (size_t)bid * 512 * ISZ;
        const int pwm = (warp >> 2) * 16;
        const int pwn = (warp & 3) * 64;
        const float sc = 1.0f / 16.0f;

        for (int mc = 0; mc < 8; mc++) {
            const int tb2 = mc * 64;
            float acc[8][4];
#pragma unroll
            for (int i = 0; i < 8; i++)
#pragma unroll
                for (int j = 0; j < 4; j++) acc[i][j] = 0.0f;

            const float* ar0 = Abase + (size_t)(tb2 + pwm + gID) * ISZ;
            const float* ar1 = ar0 + 8 * ISZ;

#pragma unroll 2
            for (int kk = 0; kk < 256; kk += 32) {
                float4 f;
                f = *(const float4*)(ar0 + kk + tig * 4);
                uint32_t a0 = pack_e4m3x4(f.x, f.y, f.z, f.w);
                f = *(const float4*)(ar1 + kk + tig * 4);
                uint32_t a1 = pack_e4m3x4(f.x, f.y, f.z, f.w);
                f = *(const float4*)(ar0 + kk + 16 + tig * 4);
                uint32_t a2 = pack_e4m3x4(f.x, f.y, f.z, f.w);
                f = *(const float4*)(ar1 + kk + 16 + tig * 4);
                uint32_t a3 = pack_e4m3x4(f.x, f.y, f.z, f.w);

                if (pwn == 0) {
                    uint8_t* d = g_batchH_f8 +
                        (size_t)(bid * 512 + tb2 + pwm + gID) * ISZ + kk + tig * 4;
                    *(uint32_t*)d = a0;
                    *(uint32_t*)(d + 16) = a2;
                    uint8_t* d1 = d + 8 * ISZ;
                    *(uint32_t*)d1 = a1;
                    *(uint32_t*)(d1 + 16) = a3;
                }
#pragma unroll
                for (int nt = 0; nt < 8; nt++) {
                    int n = pwn + nt * 8 + gID;
                    uint32_t b0 = *(uint32_t*)&WB[n * WISTR + kk + tig * 4];
                    uint32_t b1 = *(uint32_t*)&WB[n * WISTR + kk + 16 + tig * 4];
                    MMA_E4M3(acc[nt], a0, a1, a2, a3, b0, b1);
                }
            }
            const int r0 = tb2 + pwm + gID;
#pragma unroll
            for (int nt = 0; nt < 8; nt++) {
                int cb = pwn + nt * 8 + 2 * tig;
                *(uint16_t*)&sPH[r0 * PHSTR + cb] =
                    h2_to_e4m3x2(__floats2half2_rn(acc[nt][0] * sc, acc[nt][1] * sc));
                *(uint16_t*)&sPH[(r0 + 8) * PHSTR + cb] =
                    h2_to_e4m3x2(__floats2half2_rn(acc[nt][2] * sc, acc[nt][3] * sc));
            }
        }
        __syncthreads();

#pragma unroll
        for (int i = 0; i < 4; i++) {
            int linear = tid + (i << 9);
            int row = linear >> 5, c16 = (linear & 31) << 4;
            *(uint4*)&Bs8[row * XSTR + c16] =
                *(const uint4*)(g_Wcat_f8 + ((size_t)(n0 + row)) * XDIM + c16);
        }
        __syncthreads();
    }

    __half2 swl2[4];
    {
        uint4 v = *(const uint4*)(sw_h + lane * 8);
        swl2[0] = *(__half2*)&v.x; swl2[1] = *(__half2*)&v.y;
        swl2[2] = *(__half2*)&v.z; swl2[3] = *(__half2*)&v.w;
    }

    for (int s = 0; s < NSTEP; s++) {
        // ======= PHASE A: per-row-group pipelines (named barriers only) =====

        // ---- LSTM(s-1) -> h (group rg, 2 consecutive cells/thread) ----
        {
            const int row = b0 + rg;
            const int j2 = gtid * 2;
            if (s > 0) {
                const float* g = g_gates + (size_t)row * GDIM;
                float* cp = g_c + (size_t)row * HSZ;
                float2 gi = *(const float2*)&g[j2];
                float2 gf = *(const float2*)&g[j2 + 256];
                float2 gg = *(const float2*)&g[j2 + 512];
                float2 go = *(const float2*)&g[j2 + 768];
                float2 co = *(const float2*)&cp[j2];
                float cn0 = fast_sigmoid(gf.x) * co.x +
                            fast_sigmoid(gi.x) * tanh_fast(gg.x);
                float cn1 = fast_sigmoid(gf.y) * co.y +
                            fast_sigmoid(gi.y) * tanh_fast(gg.y);
                float hn0 = fast_sigmoid(go.x) * tanh_fast(cn0);
                float hn1 = fast_sigmoid(go.y) * tanh_fast(cn1);
                *(float2*)&cp[j2] = make_float2(cn0, cn1);
                __half2 hh = __floats2half2_rn(hn0, hn1);
                *(__half2*)&sh[rg * HSZ + j2] = hh;
                uint16_t hb = h2_to_e4m3x2(hh);
                *(uint16_t*)(g_X_f8 + (size_t)row * XDIM + 256 + j2) = hb;
                *(uint16_t*)(g_hs_f8 + ((size_t)row * NSTEP + (s - 1)) * HSZ + j2) = hb;
            } else {
                *(__half2*)&sh[rg * HSZ + j2] = __floats2half2_rn(0.f, 0.f);
                *(uint16_t*)(g_X_f8 + (size_t)row * XDIM + 256 + j2) = 0;
            }
        }
        bar_group(rg);

        // ---- projh partials: 4 warps of group, 64 k each (even/odd split) --
        {
            const int kb = gwarp << 6;
            __half2 accA[4], accB[4];
#pragma unroll
            for (int p = 0; p < 4; p++) {
                accA[p] = __floats2half2_rn(0.f, 0.f);
                accB[p] = accA[p];
            }
            const __half* WT = g_Wh2hT_h + (size_t)kb * HSZ + lane * 8;
            const __half* hrow = sh + rg * HSZ + kb;
#pragma unroll 4
            for (int k = 0; k < 64; k += 2) {
                uint4 wv0 = *(const uint4*)(WT + k * HSZ);
                uint4 wv1 = *(const uint4*)(WT + (k + 1) * HSZ);
                __half2 hk0 = __half2half2(hrow[k]);
                __half2 hk1 = __half2half2(hrow[k + 1]);
                accA[0] = __hfma2(*(__half2*)&wv0.x, hk0, accA[0]);
                accA[1] = __hfma2(*(__half2*)&wv0.y, hk0, accA[1]);
                accA[2] = __hfma2(*(__half2*)&wv0.z, hk0, accA[2]);
                accA[3] = __hfma2(*(__half2*)&wv0.w, hk0, accA[3]);
                accB[0] = __hfma2(*(__half2*)&wv1.x, hk1, accB[0]);
                accB[1] = __hfma2(*(__half2*)&wv1.y, hk1, accB[1]);
                accB[2] = __hfma2(*(__half2*)&wv1.z, hk1, accB[2]);
                accB[3] = __hfma2(*(__half2*)&wv1.w, hk1, accB[3]);
            }
#pragma unroll
            for (int p = 0; p < 4; p++) {
                float2 fa = __half22float2(accA[p]);
                float2 fb = __half22float2(accB[p]);
                redh[((rg * 4 + gwarp) << 7) + lane * 4 + p] =
                    __floats2half2_rn(fa.x + fb.x, fa.y + fb.y);
            }
        }
        bar_group(rg);

        // ---- reduce 4 partials -> sp_h (group rg) ----
        {
            const int j2 = gtid;   // half2 index, j pair = j2*2
            float2 sum = make_float2(0.f, 0.f);
#pragma unroll
            for (int w = 0; w < 4; w++) {
                float2 v = __half22float2(redh[((rg * 4 + w) << 7) + j2]);
                sum.x += v.x; sum.y += v.y;
            }
            float2 bv = *(const float2*)&sb[j2 * 2];
            *(__half2*)&sp_h[rg * HSZ + j2 * 2] =
                __floats2half2_rn(sum.x + bv.x, sum.y + bv.y);
        }
        bar_group(rg);

        // ---- scores: 4 warps of group, 32 t each, smem projH ----
        {
            const int tb = gwarp << 5;
            __half2 spl2[4];
            {
                uint4 v = *(const uint4*)(sp_h + rg * HSZ + lane * 8);
                spl2[0] = *(__half2*)&v.x; spl2[1] = *(__half2*)&v.y;
                spl2[2] = *(__half2*)&v.z; spl2[3] = *(__half2*)&v.w;
            }
            const uint8_t* pH = sPH + (size_t)(rg * TLEN + tb) * PHSTR + lane * 8;
            for (int t = 0; t < 32; t += 8) {
                uint2 v[8];
#pragma unroll
                for (int u = 0; u < 8; u++)
                    v[u] = *(const uint2*)(pH + (t + u) * PHSTR);
                float ac[8];
#pragma unroll
                for (int u = 0; u < 8; u++) {
                    __half2 d0 = e4m3x2_to_h2((uint16_t)(v[u].x & 0xffffu));
                    __half2 d1 = e4m3x2_to_h2((uint16_t)(v[u].x >> 16));
                    __half2 d2 = e4m3x2_to_h2((uint16_t)(v[u].y & 0xffffu));
                    __half2 d3 = e4m3x2_to_h2((uint16_t)(v[u].y >> 16));
                    __half2 prod = __floats2half2_rn(0.f, 0.f);
                    prod = __hfma2(swl2[0], tanh2(__hadd2(d0, spl2[0])), prod);
                    prod = __hfma2(swl2[1], tanh2(__hadd2(d1, spl2[1])), prod);
                    prod = __hfma2(swl2[2], tanh2(__hadd2(d2, spl2[2])), prod);
                    prod = __hfma2(swl2[3], tanh2(__hadd2(d3, spl2[3])), prod);
                    float2 f = __half22float2(prod);
                    ac[u] = f.x + f.y;
                }
#pragma unroll
                for (int u = 0; u < 8; u += 2) {
                    __half2 pk = __floats2half2_rn(ac[u], ac[u + 1]);
                    uint32_t pu = *(uint32_t*)&pk;
#pragma unroll
                    for (int o = 16; o; o >>= 1) {
                        uint32_t other = __shfl_xor_sync(0xffffffffu, pu, o);
                        __half2 a = *(__half2*)&pu, b2 = *(__half2*)&other;
                        __half2 s2 = __hadd2(a, b2);
                        pu = *(uint32_t*)&s2;
                    }
                    if (lane == 0) {
                        float2 f = __half22float2(*(__half2*)&pu);
                        se[rg * TLEN + tb + t + u] = f.x;
                        se[rg * TLEN + tb + t + u + 1] = f.y;
                    }
                }
            }
        }
        bar_group(rg);

        // ---- softmax -> seh (first warp of group) ----
        if (gwarp == 0) {
            const float* sr = se + rg * TLEN;
            float v0 = sr[lane], v1 = sr[lane + 32];
            float v2 = sr[lane + 64], v3 = sr[lane + 96];
            float mx = fmaxf(fmaxf(v0, v1), fmaxf(v2, v3));
#pragma unroll
            for (int o = 16; o; o >>= 1) mx = fmaxf(mx, __shfl_xor_sync(0xffffffffu, mx, o));
            float e0 = __expf(v0 - mx), e1 = __expf(v1 - mx);
            float e2 = __expf(v2 - mx), e3 = __expf(v3 - mx);
            float sum = e0 + e1 + e2 + e3;
#pragma unroll
            for (int o = 16; o; o >>= 1) sum += __shfl_xor_sync(0xffffffffu, sum, o);
            float inv = 1.0f / sum;
            __half2* dr = seh + rg * TLEN;
            dr[lane]      = __float2half2_rn(e0 * inv);
            dr[lane + 32] = __float2half2_rn(e1 * inv);
            dr[lane + 64] = __float2half2_rn(e2 * inv);
            dr[lane + 96] = __float2half2_rn(e3 * inv);
        }
        bar_group(rg);

        // ---- context: group rg, vectorized 8B loads, 4-way t-split ----
        {
            const int ci8 = gtid & 31;          // 8-i column group
            const int tq = gtid >> 5;           // t quarter
            const uint8_t* bH = g_batchH_f8 + (size_t)(b0 + rg) * TLEN * ISZ + ci8 * 8;
            const __half2* al = seh + rg * TLEN + tq * 32;
            const uint8_t* bHt = bH + tq * 32 * ISZ;
            __half2 a0 = __floats2half2_rn(0.f, 0.f);
            __half2 a1 = a0, a2 = a0, a3 = a0;
#pragma unroll 8
            for (int t = 0; t < 32; t++) {
                uint2 v = *(const uint2*)(bHt + t * ISZ);
                __half2 alv = al[t];
                a0 = __hfma2(alv, e4m3x2_to_h2((uint16_t)(v.x & 0xffffu)), a0);
                a1 = __hfma2(alv, e4m3x2_to_h2((uint16_t)(v.x >> 16)), a1);
                a2 = __hfma2(alv, e4m3x2_to_h2((uint16_t)(v.y & 0xffffu)), a2);
                a3 = __hfma2(alv, e4m3x2_to_h2((uint16_t)(v.y >> 16)), a3);
            }
            int base = rg * 32 + ci8;
            redh[(tq * 4 + 0) * CSTR + base] = a0;
            redh[(tq * 4 + 1) * CSTR + base] = a1;
            redh[(tq * 4 + 2) * CSTR + base] = a2;
            redh[(tq * 4 + 3) * CSTR + base] = a3;
        }
        bar_group(rg);
        {
            const int ci2 = gtid;
            const int ci8 = ci2 >> 2, p = ci2 & 3;
            const int base = rg * 32 + ci8;
            __half2 s0 = redh[(0 * 4 + p) * CSTR + base];
            __half2 s1 = redh[(1 * 4 + p) * CSTR + base];
            __half2 s2 = redh[(2 * 4 + p) * CSTR + base];
            __half2 s3 = redh[(3 * 4 + p) * CSTR + base];
            __half2 sum = __hadd2(__hadd2(s0, s1), __hadd2(s2, s3));
            *(uint16_t*)(g_X_f8 + (size_t)(b0 + rg) * XDIM + ci8 * 8 + p * 2) =
                h2_to_e4m3x2(sum);
        }

        group_sync(grp);   // X ready within group (also block-wide sync)

        // ==== gates tile = (X[m0:+64] @ Wcat[n0:+64]^T)/16, e4m3 MMA ====
        {
#pragma unroll
            for (int i = 0; i < 4; i++) {
                int linear = tid + (i << 9);
                int row = linear >> 5, c16 = (linear & 31) << 4;
                *(uint4*)&As8[row * XSTR + c16] =
                    *(const uint4*)(g_X_f8 + ((size_t)(m0 + row)) * XDIM + c16);
            }
            __syncthreads();

            float acc[2][4];
#pragma unroll
            for (int i = 0; i < 2; i++)
#pragma unroll
                for (int j = 0; j < 4; j++) acc[i][j] = 0.0f;

#pragma unroll 4
            for (int kk = 0; kk < 512; kk += 32) {
                uint32_t a0 = *(uint32_t*)&As8[(wm4 + gID) * XSTR + kk + tig * 4];
                uint32_t a1 = *(uint32_t*)&As8[(wm4 + gID + 8) * XSTR + kk + tig * 4];
                uint32_t a2 = *(uint32_t*)&As8[(wm4 + gID) * XSTR + kk + 16 + tig * 4];
                uint32_t a3 = *(uint32_t*)&As8[(wm4 + gID + 8) * XSTR + kk + 16 + tig * 4];
#pragma unroll
                for (int nt = 0; nt < 2; nt++) {
                    uint32_t b0 = *(uint32_t*)&Bs8[(wn4 + nt * 8 + gID) * XSTR + kk + tig * 4];
                    uint32_t b1 = *(uint32_t*)&Bs8[(wn4 + nt * 8 + gID) * XSTR + kk + 16 + tig * 4];
                    MMA_E4M3(acc[nt], a0, a1, a2, a3, b0, b1);
                }
            }

            const int r0 = m0 + wm4 + gID, r1 = r0 + 8;
            int tgt0 = text[r0 * NSTEP + s];
            int tgt1 = text[r1 * NSTEP + s];
            const float* e0 = g_Wemb + (size_t)tgt0 * GDIM;
            const float* e1 = g_Wemb + (size_t)tgt1 * GDIM;
            const float sc = 1.0f / 16.0f;
#pragma unroll
            for (int nt = 0; nt < 2; nt++) {
                int cbase = n0 + wn4 + nt * 8 + 2 * tig;
                float2 w0 = *(const float2*)(e0 + cbase);
                float2 w1 = *(const float2*)(e1 + cbase);
                float2 o0 = make_float2(acc[nt][0] * sc + w0.x, acc[nt][1] * sc + w0.y);
                float2 o1 = make_float2(acc[nt][2] * sc + w1.x, acc[nt][3] * sc + w1.y);
                *(float2*)&g_gates[(size_t)r0 * GDIM + cbase] = o0;
                *(float2*)&g_gates[(size_t)r1 * GDIM + cbase] = o1;
            }
        }

        group_sync(grp);   // gates ready within group
    }

    // final LSTM -> hs[25]
    {
        const int row = b0 + rg;
        const int j2 = gtid * 2;
        const float* g = g_gates + (size_t)row * GDIM;
        const float* cp = g_c + (size_t)row * HSZ;
        float2 gi = *(const float2*)&g[j2];
        float2 gf = *(const float2*)&g[j2 + 256];
        float2 gg = *(const float2*)&g[j2 + 512];
        float2 go = *(const float2*)&g[j2 + 768];
        float2 co = *(const float2*)&cp[j2];
        float cn0 = fast_sigmoid(gf.x) * co.x + fast_sigmoid(gi.x) * tanh_fast(gg.x);
        float cn1 = fast_sigmoid(gf.y) * co.y + fast_sigmoid(gi.y) * tanh_fast(gg.y);
        float hn0 = fast_sigmoid(go.x) * tanh_fast(cn0);
        float hn1 = fast_sigmoid(go.y) * tanh_fast(cn1);
        *(uint16_t*)(g_hs_f8 + ((size_t)row * NSTEP + (NSTEP - 1)) * HSZ + j2) =
            h2_to_e4m3x2(__floats2half2_rn(hn0, hn1));
    }
}

// ------------------------- launch -------------------------------------------
extern "C" void kernel_launch(void* const* d_in, const int* in_sizes, int n_in,
                              void* d_out, int out_size) {
    const float* batch_H = (const float*)d_in[0];
    const int*   text    = (const int*)d_in[1];
    const float* W_i2h   = (const float*)d_in[3];
    const float* W_h2h   = (const float*)d_in[4];
    const float* b_h2h   = (const float*)d_in[5];
    const float* W_score = (const float*)d_in[6];
    const float* W_ih    = (const float*)d_in[7];
    const float* W_hh    = (const float*)d_in[8];
    const float* b_ih    = (const float*)d_in[9];
    const float* b_hh    = (const float*)d_in[10];
    const float* W_gen   = (const float*)d_in[11];
    const float* b_gen   = (const float*)d_in[12];
    float* out = (float*)d_out;

    uint8_t *Wgen_f8, *hs_f8;
    cudaGetSymbolAddress((void**)&Wgen_f8, g_Wgen_f8);
    cudaGetSymbolAddress((void**)&hs_f8,   g_hs_f8);

    static bool attr_set = false;
    if (!attr_set) {
        cudaFuncSetAttribute(persistent_steps,
                             cudaFuncAttributeMaxDynamicSharedMemorySize,
                             SMEM_BYTES);
        attr_set = true;
    }

    init_kernel<<<2048, 256>>>(W_ih, W_hh, b_ih, b_hh, W_i2h, W_h2h, W_gen);

    persistent_steps<<<NBLK, NTHR, SMEM_BYTES>>>(batch_H, text, b_h2h, W_score);

    qgemm_logits<<<dim3(2, 104), 256>>>(
        hs_f8, Wgen_f8, out, BSZ * NSTEP, NCLS, HSZ, HSZ, HSZ, NCLS, b_gen);
}

// round 14
// speedup vs baseline: 1.0677x; 1.0677x over previous
#include <cuda_runtime.h>
#include <cuda_fp16.h>
#include <cstdint>

#define BSZ   512
#define TLEN  128
#define ISZ   256
#define HSZ   256
#define NCLS  100
#define NSTEP 26
#define XDIM  512
#define GDIM  1024
#define WIH_LD 356
#define BLANK_ID 3
#define RPB   4
#define NBLK  128
#define GRPBLK 32
#define NTHR  512
#define XSTR  528            // gates smem slab row stride (bytes), 16-aligned
#define PHSTR 272            // projH smem row stride (bytes), 16-aligned
#define WISTR 264            // Wi2h staging stride (bytes), 8-aligned ONLY
#define TAIL_BYTES (2048 + 2048 + 512 + 1024 + 2048 + 2048)
#define SMEM_BYTES (512 * PHSTR + 2 * 64 * XSTR + TAIL_BYTES)   // 216576

// ------------------------- device scratch -----------------------------------
__device__ uint8_t g_batchH_f8[BSZ * TLEN * ISZ];
__device__ uint8_t g_X_f8[BSZ * XDIM];
__device__ float  g_gates[BSZ * GDIM];
__device__ float  g_c[BSZ * HSZ];
__device__ uint8_t g_hs_f8[BSZ * NSTEP * HSZ];
__device__ uint8_t g_Wcat_f8[GDIM * XDIM];     // x16 scaled
__device__ uint8_t g_Wi2h_f8[HSZ * ISZ];       // x16 scaled
__device__ uint8_t g_Wgen_f8[NCLS * HSZ];      // x16 scaled
__device__ __half g_Wh2hT_h[HSZ * HSZ];
__device__ float  g_Wemb[NCLS * GDIM];
__device__ unsigned g_count[4 * 32];
__device__ volatile unsigned g_epoch[4 * 32];

// ------------------------- fast math ----------------------------------------
__device__ __forceinline__ float tanh_fast(float x) {
    float y;
    asm("tanh.approx.f32 %0, %1;" : "=f"(y) : "f"(x));
    return y;
}
__device__ __forceinline__ float fast_sigmoid(float x) {
    return 0.5f * (1.0f + tanh_fast(0.5f * x));
}
__device__ __forceinline__ __half2 tanh2(__half2 x) {
    uint32_t xi = *(uint32_t*)&x, yo;
    asm("tanh.approx.f16x2 %0, %1;" : "=r"(yo) : "r"(xi));
    return *(__half2*)&yo;
}
__device__ __forceinline__ uint16_t h2_to_e4m3x2(__half2 h) {
    uint16_t r;
    asm("cvt.rn.satfinite.e4m3x2.f16x2 %0, %1;" : "=h"(r) : "r"(*(uint32_t*)&h));
    return r;
}
__device__ __forceinline__ __half2 e4m3x2_to_h2(uint16_t b) {
    uint32_t r;
    asm("cvt.rn.f16x2.e4m3x2 %0, %1;" : "=r"(r) : "h"(b));
    return *(__half2*)&r;
}
__device__ __forceinline__ uint8_t f32_to_e4m3(float v) {
    return (uint8_t)h2_to_e4m3x2(__floats2half2_rn(v, v));
}
__device__ __forceinline__ uint32_t pack_e4m3x4(float a, float b, float c, float d) {
    return (uint32_t)h2_to_e4m3x2(__floats2half2_rn(a, b)) |
           ((uint32_t)h2_to_e4m3x2(__floats2half2_rn(c, d)) << 16);
}
__device__ __forceinline__ __half2 shfl_hadd2(__half2 v, int o) {
    uint32_t u = *(uint32_t*)&v;
    uint32_t w = __shfl_xor_sync(0xffffffffu, u, o);
    return __hadd2(v, *(__half2*)&w);
}
#define MMA_E4M3(acc, a0, a1, a2, a3, b0, b1)                                  \
    asm volatile(                                                              \
        "mma.sync.aligned.m16n8k32.row.col.f32.e4m3.e4m3.f32 "                 \
        "{%0,%1,%2,%3}, {%4,%5,%6,%7}, {%8,%9}, {%0,%1,%2,%3};"                \
        : "+f"(acc[0]), "+f"(acc[1]), "+f"(acc[2]), "+f"(acc[3])               \
        : "r"(a0), "r"(a1), "r"(a2), "r"(a3), "r"(b0), "r"(b1))

// ------------------------- group barrier (32 blocks) -------------------------
__device__ __forceinline__ void group_sync(int g) {
    __syncthreads();
    if (threadIdx.x == 0) {
        const int slot = g * 32;
        unsigned my = g_epoch[slot];
        __threadfence();
        unsigned old = atomicAdd(&g_count[slot], 1u);
        if (old == GRPBLK - 1) {
            g_count[slot] = 0;
            __threadfence();
            g_epoch[slot] = my + 1;
        } else {
            while (g_epoch[slot] == my) { __nanosleep(16); }
            __threadfence();
        }
    }
    __syncthreads();
}

// ------------------------- init ----------------------------------------------
__global__ void init_kernel(const float* __restrict__ W_ih,
                            const float* __restrict__ W_hh,
                            const float* __restrict__ b_ih,
                            const float* __restrict__ b_hh,
                            const float* __restrict__ W_i2h,
                            const float* __restrict__ W_h2h,
                            const float* __restrict__ W_gen) {
    int idx = blockIdx.x * 256 + threadIdx.x;
    if (idx < GDIM * XDIM) {
        int j = idx >> 9, k = idx & 511;
        float v = (k < 256) ? W_ih[j * WIH_LD + k] : W_hh[j * 256 + (k - 256)];
        g_Wcat_f8[idx] = f32_to_e4m3(v * 16.0f);
    }
    if (idx < HSZ * HSZ) {
        int j = idx >> 8, k = idx & 255;
        g_Wh2hT_h[k * HSZ + j] = __float2half_rn(W_h2h[idx]);
        g_Wi2h_f8[idx] = f32_to_e4m3(W_i2h[idx] * 16.0f);
    }
    if (idx < NCLS * HSZ) g_Wgen_f8[idx] = f32_to_e4m3(W_gen[idx] * 16.0f);
    if (idx < NCLS * GDIM) {
        int cls = idx >> 10, c = idx & 1023;
        g_Wemb[idx] = W_ih[(size_t)c * WIH_LD + 256 + cls] + b_ih[c] + b_hh[c];
    }
    if (idx < BSZ * HSZ) g_c[idx] = 0.0f;
}

// ------------------------- e4m3 MMA GEMM (logits), tile 128x64 ---------------
__global__ __launch_bounds__(256) void qgemm_logits(
    const uint8_t* __restrict__ Aptr, const uint8_t* __restrict__ Bw,
    float* __restrict__ Cm,
    int M, int N, int K, int lda, int ldb, int ldc,
    const float* __restrict__ bias) {

    __shared__ uint8_t As[128 * 80];
    __shared__ uint8_t Bs[64 * 80];

    const int m0 = blockIdx.y * 128, n0 = blockIdx.x * 64;
    const int tid = threadIdx.x, lane = tid & 31, warp = tid >> 5;
    const int wm = (warp >> 1) * 32, wn = (warp & 1) * 32;
    const int gID = lane >> 2, tig = lane & 3;
    const int ar = tid >> 1, aoff = (tid & 1) << 5;
    const int br = tid >> 2, boff = (tid & 3) << 4;

    float acc[2][4][4];
#pragma unroll
    for (int mf = 0; mf < 2; mf++)
#pragma unroll
        for (int i = 0; i < 4; i++)
#pragma unroll
            for (int j = 0; j < 4; j++) acc[mf][i][j] = 0.0f;

    auto loadA = [&](int k0, uint4& o0, uint4& o1) {
        const uint8_t* p = Aptr + (size_t)(m0 + ar) * lda + k0 + aoff;
        o0 = *(const uint4*)p;
        o1 = *(const uint4*)(p + 16);
    };
    auto loadB = [&](int k0) -> uint4 {
        if (n0 + br < N)
            return *(const uint4*)(Bw + (size_t)(n0 + br) * ldb + k0 + boff);
        return make_uint4(0u, 0u, 0u, 0u);
    };

    uint4 a0R, a1R, bR;
    loadA(0, a0R, a1R);
    bR = loadB(0);
    const int iters = K >> 6;

    for (int it = 0; it < iters; it++) {
        __syncthreads();
        *(uint4*)&As[ar * 80 + aoff] = a0R;
        *(uint4*)&As[ar * 80 + aoff + 16] = a1R;
        *(uint4*)&Bs[br * 80 + boff] = bR;
        __syncthreads();
        if (it + 1 < iters) {
            loadA((it + 1) << 6, a0R, a1R);
            bR = loadB((it + 1) << 6);
        }
#pragma unroll
        for (int kk = 0; kk < 64; kk += 32) {
            uint32_t af[2][4];
#pragma unroll
            for (int mf = 0; mf < 2; mf++) {
                int rb = wm + mf * 16 + gID;
                af[mf][0] = *(uint32_t*)&As[rb * 80 + kk + tig * 4];
                af[mf][1] = *(uint32_t*)&As[(rb + 8) * 80 + kk + tig * 4];
                af[mf][2] = *(uint32_t*)&As[rb * 80 + kk + 16 + tig * 4];
                af[mf][3] = *(uint32_t*)&As[(rb + 8) * 80 + kk + 16 + tig * 4];
            }
#pragma unroll
            for (int nt = 0; nt < 4; nt++) {
                uint32_t b0 = *(uint32_t*)&Bs[(wn + nt * 8 + gID) * 80 + kk + tig * 4];
                uint32_t b1 = *(uint32_t*)&Bs[(wn + nt * 8 + gID) * 80 + kk + 16 + tig * 4];
#pragma unroll
                for (int mf = 0; mf < 2; mf++)
                    MMA_E4M3(acc[mf][nt], af[mf][0], af[mf][1], af[mf][2],
                             af[mf][3], b0, b1);
            }
        }
    }

    const float sc = 1.0f / 16.0f;
#pragma unroll
    for (int mf = 0; mf < 2; mf++) {
        const int r0 = m0 + wm + mf * 16 + gID, r1 = r0 + 8;
#pragma unroll
        for (int nt = 0; nt < 4; nt++) {
            int cb = n0 + wn + nt * 8 + 2 * tig;
#pragma unroll
            for (int hr = 0; hr < 2; hr++) {
                int r = hr ? r1 : r0;
                if (r >= M || cb >= N) continue;
                float v0 = acc[mf][nt][hr * 2 + 0] * sc + bias[cb];
                float v1 = acc[mf][nt][hr * 2 + 1] * sc + bias[cb + 1];
                if (cb == BLANK_ID) v0 = -10000.0f;
                if (cb + 1 == BLANK_ID) v1 = -10000.0f;
                *(float2*)(Cm + (size_t)r * ldc + cb) = make_float2(v0, v1);
            }
        }
    }
}

// ------------------------- persistent kernel: prolog + 26 steps --------------
__global__ __launch_bounds__(NTHR, 1) void persistent_steps(
    const float* __restrict__ batch_H, const int* __restrict__ text,
    const float* __restrict__ b_h2h, const float* __restrict__ wscore) {

    extern __shared__ char dyn[];
    uint8_t* sPH = (uint8_t*)dyn;                       // [512][PHSTR]
    uint8_t* Bs8 = sPH + 512 * PHSTR;                   // [64][XSTR]
    uint8_t* As8 = Bs8 + 64 * XSTR;                     // [64][XSTR]
    __half2* redh = (__half2*)As8;                      // overlay (phase A)
    char* tail = (char*)(As8 + 64 * XSTR);
    __half*  sh   = (__half*)tail;                      // [4][256]
    __half*  sp_h = sh + 1024;                          // [4][256]
    __half*  sw_h = sp_h + 1024;                        // [256]
    float*   sb   = (float*)(sw_h + 256);               // [256]
    float*   se   = sb + 256;                           // [4][128]
    __half2* seh  = (__half2*)(se + 512);               // [4][128]

    const int tid = threadIdx.x, lane = tid & 31, warp = tid >> 5;
    const int bid = blockIdx.x;
    const int grp = bid >> 5;
    const int lid = bid & 31;
    const int b0 = bid * RPB;
    const int m0 = grp * 128 + (lid >> 4) * 64;
    const int n0 = (lid & 15) * 64;
    const int wm4 = (warp >> 2) * 16, wn4 = (warp & 3) * 16;
    const int gID = lane >> 2, tig = lane & 3;

    if (tid < 256) {
        sw_h[tid] = __float2half_rn(wscore[tid]);
        sb[tid] = b_h2h[tid];
    }

    // ========== PROLOG: projH slice -> sPH, batch_H -> g_batchH_f8 ==========
    {
        uint8_t* WB = Bs8;
#pragma unroll
        for (int i = 0; i < 8; i++) {
            int linear = tid + (i << 9);
            int row = linear >> 4, c = (linear & 15) << 4;
            uint4 v = *(const uint4*)(g_Wi2h_f8 + row * 256 + c);
            *(uint2*)&WB[row * WISTR + c] = make_uint2(v.x, v.y);
            *(uint2*)&WB[row * WISTR + c + 8] = make_uint2(v.z, v.w);
        }
        __syncthreads();

        const float* Abase = batch_H + (size_t)bid * 512 * ISZ;
        const int pwm = (warp >> 2) * 16;
        const int pwn = (warp & 3) * 64;
        const float sc = 1.0f / 16.0f;

        for (int mc = 0; mc < 8; mc++) {
            const int tb2 = mc * 64;
            float acc[8][4];
#pragma unroll
            for (int i = 0; i < 8; i++)
#pragma unroll
                for (int j = 0; j < 4; j++) acc[i][j] = 0.0f;

            const float* ar0 = Abase + (size_t)(tb2 + pwm + gID) * ISZ;
            const float* ar1 = ar0 + 8 * ISZ;

#pragma unroll 2
            for (int kk = 0; kk < 256; kk += 32) {
                float4 f;
                f = *(const float4*)(ar0 + kk + tig * 4);
                uint32_t a0 = pack_e4m3x4(f.x, f.y, f.z, f.w);
                f = *(const float4*)(ar1 + kk + tig * 4);
                uint32_t a1 = pack_e4m3x4(f.x, f.y, f.z, f.w);
                f = *(const float4*)(ar0 + kk + 16 + tig * 4);
                uint32_t a2 = pack_e4m3x4(f.x, f.y, f.z, f.w);
                f = *(const float4*)(ar1 + kk + 16 + tig * 4);
                uint32_t a3 = pack_e4m3x4(f.x, f.y, f.z, f.w);

                if (pwn == 0) {
                    uint8_t* d = g_batchH_f8 +
                        (size_t)(bid * 512 + tb2 + pwm + gID) * ISZ + kk + tig * 4;
                    *(uint32_t*)d = a0;
                    *(uint32_t*)(d + 16) = a2;
                    uint8_t* d1 = d + 8 * ISZ;
                    *(uint32_t*)d1 = a1;
                    *(uint32_t*)(d1 + 16) = a3;
                }
#pragma unroll
                for (int nt = 0; nt < 8; nt++) {
                    int n = pwn + nt * 8 + gID;
                    uint32_t b0 = *(uint32_t*)&WB[n * WISTR + kk + tig * 4];
                    uint32_t b1 = *(uint32_t*)&WB[n * WISTR + kk + 16 + tig * 4];
                    MMA_E4M3(acc[nt], a0, a1, a2, a3, b0, b1);
                }
            }
            const int r0 = tb2 + pwm + gID;
#pragma unroll
            for (int nt = 0; nt < 8; nt++) {
                int cb = pwn + nt * 8 + 2 * tig;
                *(uint16_t*)&sPH[r0 * PHSTR + cb] =
                    h2_to_e4m3x2(__floats2half2_rn(acc[nt][0] * sc, acc[nt][1] * sc));
                *(uint16_t*)&sPH[(r0 + 8) * PHSTR + cb] =
                    h2_to_e4m3x2(__floats2half2_rn(acc[nt][2] * sc, acc[nt][3] * sc));
            }
        }
        __syncthreads();

#pragma unroll
        for (int i = 0; i < 4; i++) {
            int linear = tid + (i << 9);
            int row = linear >> 5, c16 = (linear & 31) << 4;
            *(uint4*)&Bs8[row * XSTR + c16] =
                *(const uint4*)(g_Wcat_f8 + ((size_t)(n0 + row)) * XDIM + c16);
        }
        __syncthreads();
    }

    __half2 swl2[4];
    {
        uint4 v = *(const uint4*)(sw_h + lane * 8);
        swl2[0] = *(__half2*)&v.x; swl2[1] = *(__half2*)&v.y;
        swl2[2] = *(__half2*)&v.z; swl2[3] = *(__half2*)&v.w;
    }

    // context phase lane mapping (fixed per thread)
    const int cw_r = warp >> 2;            // row
    const int ctq = lane >> 3;             // t-quarter
    const int cci8 = (warp & 3) * 8 + (lane & 7);   // 8-byte i-group 0..31
    const uint8_t* cbHt = g_batchH_f8 +
        (size_t)(b0 + cw_r) * TLEN * ISZ + (size_t)(ctq * 32) * ISZ + cci8 * 8;

    for (int s = 0; s < NSTEP; s++) {
        // ==== LSTM(s-1) -> h : float2 loads, 2 consecutive cells/thread ====
        {
            const int r = tid >> 7, jb = tid & 127;
            const int row = b0 + r;
            const int j2 = jb * 2;
            if (s > 0) {
                const float* g = g_gates + (size_t)row * GDIM;
                float* cp = g_c + (size_t)row * HSZ;
                float2 gi = *(const float2*)&g[j2];
                float2 gf = *(const float2*)&g[j2 + 256];
                float2 gg = *(const float2*)&g[j2 + 512];
                float2 go = *(const float2*)&g[j2 + 768];
                float2 co = *(const float2*)&cp[j2];
                float cn0 = fast_sigmoid(gf.x) * co.x +
                            fast_sigmoid(gi.x) * tanh_fast(gg.x);
                float cn1 = fast_sigmoid(gf.y) * co.y +
                            fast_sigmoid(gi.y) * tanh_fast(gg.y);
                float hn0 = fast_sigmoid(go.x) * tanh_fast(cn0);
                float hn1 = fast_sigmoid(go.y) * tanh_fast(cn1);
                *(float2*)&cp[j2] = make_float2(cn0, cn1);
                __half2 hh = __floats2half2_rn(hn0, hn1);
                *(__half2*)&sh[r * HSZ + j2] = hh;
                uint16_t hb = h2_to_e4m3x2(hh);
                *(uint16_t*)(g_X_f8 + (size_t)row * XDIM + 256 + j2) = hb;
                *(uint16_t*)(g_hs_f8 + ((size_t)row * NSTEP + (s - 1)) * HSZ + j2) = hb;
            } else {
                *(__half2*)&sh[r * HSZ + j2] = __floats2half2_rn(0.f, 0.f);
                *(uint16_t*)(g_X_f8 + (size_t)row * XDIM + 256 + j2) = 0;
            }
        }
        __syncthreads();

        // ==== projh partials: warp w covers k in [w*16, +16) ====
        {
            const int kb = warp << 4;
            __half2 acc2[RPB][4];
#pragma unroll
            for (int r = 0; r < RPB; r++)
#pragma unroll
                for (int p = 0; p < 4; p++)
                    acc2[r][p] = __floats2half2_rn(0.f, 0.f);

            const __half* WT = g_Wh2hT_h + (size_t)kb * HSZ + lane * 8;
#pragma unroll 4
            for (int k = 0; k < 16; k++) {
                uint4 wv = *(const uint4*)(WT + k * HSZ);
                __half2 wh[4];
                wh[0] = *(__half2*)&wv.x; wh[1] = *(__half2*)&wv.y;
                wh[2] = *(__half2*)&wv.z; wh[3] = *(__half2*)&wv.w;
#pragma unroll
                for (int r = 0; r < RPB; r++) {
                    __half2 hk2 = __half2half2(sh[r * HSZ + kb + k]);
#pragma unroll
                    for (int p = 0; p < 4; p++)
                        acc2[r][p] = __hfma2(wh[p], hk2, acc2[r][p]);
                }
            }
#pragma unroll
            for (int r = 0; r < RPB; r++)
#pragma unroll
                for (int p = 0; p < 4; p++)
                    redh[((warp * RPB + r) << 7) + lane * 4 + p] = acc2[r][p];
        }
        __syncthreads();

        // ==== reduce 16 partials -> sp_h ====
        {
            const int r = tid >> 7, j2 = tid & 127;
            float2 sum = make_float2(0.f, 0.f);
#pragma unroll
            for (int w = 0; w < 16; w++) {
                float2 v = __half22float2(redh[(((w * RPB + r)) << 7) + j2]);
                sum.x += v.x; sum.y += v.y;
            }
            float2 bv = *(const float2*)&sb[j2 * 2];
            *(__half2*)&sp_h[r * HSZ + j2 * 2] =
                __floats2half2_rn(sum.x + bv.x, sum.y + bv.y);
        }
        __syncthreads();

        // ==== scores: 4 warps/row, 32 t each, smem projH, packed reduce ====
        {
            const int r = warp >> 2;
            const int tb = (warp & 3) << 5;
            __half2 spl2[4];
            {
                uint4 v = *(const uint4*)(sp_h + r * HSZ + lane * 8);
                spl2[0] = *(__half2*)&v.x; spl2[1] = *(__half2*)&v.y;
                spl2[2] = *(__half2*)&v.z; spl2[3] = *(__half2*)&v.w;
            }
            const uint8_t* pH = sPH + (size_t)(r * TLEN + tb) * PHSTR + lane * 8;
            for (int t = 0; t < 32; t += 8) {
                uint2 v[8];
#pragma unroll
                for (int u = 0; u < 8; u++)
                    v[u] = *(const uint2*)(pH + (t + u) * PHSTR);
                float ac[8];
#pragma unroll
                for (int u = 0; u < 8; u++) {
                    __half2 d0 = e4m3x2_to_h2((uint16_t)(v[u].x & 0xffffu));
                    __half2 d1 = e4m3x2_to_h2((uint16_t)(v[u].x >> 16));
                    __half2 d2 = e4m3x2_to_h2((uint16_t)(v[u].y & 0xffffu));
                    __half2 d3 = e4m3x2_to_h2((uint16_t)(v[u].y >> 16));
                    __half2 prod = __floats2half2_rn(0.f, 0.f);
                    prod = __hfma2(swl2[0], tanh2(__hadd2(d0, spl2[0])), prod);
                    prod = __hfma2(swl2[1], tanh2(__hadd2(d1, spl2[1])), prod);
                    prod = __hfma2(swl2[2], tanh2(__hadd2(d2, spl2[2])), prod);
                    prod = __hfma2(swl2[3], tanh2(__hadd2(d3, spl2[3])), prod);
                    float2 f = __half22float2(prod);
                    ac[u] = f.x + f.y;
                }
#pragma unroll
                for (int u = 0; u < 8; u += 2) {
                    __half2 pk = __floats2half2_rn(ac[u], ac[u + 1]);
                    uint32_t pu = *(uint32_t*)&pk;
#pragma unroll
                    for (int o = 16; o; o >>= 1) {
                        uint32_t other = __shfl_xor_sync(0xffffffffu, pu, o);
                        __half2 a = *(__half2*)&pu, b2 = *(__half2*)&other;
                        __half2 s2 = __hadd2(a, b2);
                        pu = *(uint32_t*)&s2;
                    }
                    if (lane == 0) {
                        float2 f = __half22float2(*(__half2*)&pu);
                        se[r * TLEN + tb + t + u] = f.x;
                        se[r * TLEN + tb + t + u + 1] = f.y;
                    }
                }
            }
        }

        // ==== prefetch context loads (no alpha dependency) ====
        uint2 pf[8];
#pragma unroll
        for (int u = 0; u < 8; u++)
            pf[u] = *(const uint2*)(cbHt + u * ISZ);

        __syncthreads();

        // ==== softmax -> seh (warps 0..3) ====
        if (warp < RPB) {
            const float* sr = se + warp * TLEN;
            float v0 = sr[lane], v1 = sr[lane + 32];
            float v2 = sr[lane + 64], v3 = sr[lane + 96];
            float mx = fmaxf(fmaxf(v0, v1), fmaxf(v2, v3));
#pragma unroll
            for (int o = 16; o; o >>= 1) mx = fmaxf(mx, __shfl_xor_sync(0xffffffffu, mx, o));
            float e0 = __expf(v0 - mx), e1 = __expf(v1 - mx);
            float e2 = __expf(v2 - mx), e3 = __expf(v3 - mx);
            float sum = e0 + e1 + e2 + e3;
#pragma unroll
            for (int o = 16; o; o >>= 1) sum += __shfl_xor_sync(0xffffffffu, sum, o);
            float inv = 1.0f / sum;
            __half2* dr = seh + warp * TLEN;
            dr[lane]      = __float2half2_rn(e0 * inv);
            dr[lane + 32] = __float2half2_rn(e1 * inv);
            dr[lane + 64] = __float2half2_rn(e2 * inv);
            dr[lane + 96] = __float2half2_rn(e3 * inv);
        }
        __syncthreads();

        // ==== context: prefetched + streamed, warp-local tq reduction ====
        {
            const __half2* al = seh + cw_r * TLEN + ctq * 32;
            __half2 a0 = __floats2half2_rn(0.f, 0.f);
            __half2 a1 = a0, a2 = a0, a3 = a0;
#pragma unroll
            for (int u = 0; u < 8; u++) {
                __half2 alv = al[u];
                a0 = __hfma2(alv, e4m3x2_to_h2((uint16_t)(pf[u].x & 0xffffu)), a0);
                a1 = __hfma2(alv, e4m3x2_to_h2((uint16_t)(pf[u].x >> 16)), a1);
                a2 = __hfma2(alv, e4m3x2_to_h2((uint16_t)(pf[u].y & 0xffffu)), a2);
                a3 = __hfma2(alv, e4m3x2_to_h2((uint16_t)(pf[u].y >> 16)), a3);
            }
#pragma unroll 8
            for (int t = 8; t < 32; t++) {
                uint2 v = *(const uint2*)(cbHt + t * ISZ);
                __half2 alv = al[t];
                a0 = __hfma2(alv, e4m3x2_to_h2((uint16_t)(v.x & 0xffffu)), a0);
                a1 = __hfma2(alv, e4m3x2_to_h2((uint16_t)(v.x >> 16)), a1);
                a2 = __hfma2(alv, e4m3x2_to_h2((uint16_t)(v.y & 0xffffu)), a2);
                a3 = __hfma2(alv, e4m3x2_to_h2((uint16_t)(v.y >> 16)), a3);
            }
            // reduce across tq (lanes differ in bits 3,4)
            a0 = shfl_hadd2(a0, 8);  a0 = shfl_hadd2(a0, 16);
            a1 = shfl_hadd2(a1, 8);  a1 = shfl_hadd2(a1, 16);
            a2 = shfl_hadd2(a2, 8);  a2 = shfl_hadd2(a2, 16);
            a3 = shfl_hadd2(a3, 8);  a3 = shfl_hadd2(a3, 16);
            if (ctq == 0) {
                uint2 outv;
                outv.x = (uint32_t)h2_to_e4m3x2(a0) |
                         ((uint32_t)h2_to_e4m3x2(a1) << 16);
                outv.y = (uint32_t)h2_to_e4m3x2(a2) |
                         ((uint32_t)h2_to_e4m3x2(a3) << 16);
                *(uint2*)(g_X_f8 + (size_t)(b0 + cw_r) * XDIM + cci8 * 8) = outv;
            }
        }

        group_sync(grp);   // X ready within group

        // ==== gates tile = (X[m0:+64] @ Wcat[n0:+64]^T)/16, e4m3 MMA ====
        {
#pragma unroll
            for (int i = 0; i < 4; i++) {
                int linear = tid + (i << 9);
                int row = linear >> 5, c16 = (linear & 31) << 4;
                *(uint4*)&As8[row * XSTR + c16] =
                    *(const uint4*)(g_X_f8 + ((size_t)(m0 + row)) * XDIM + c16);
            }
            __syncthreads();

            float acc[2][4];
#pragma unroll
            for (int i = 0; i < 2; i++)
#pragma unroll
                for (int j = 0; j < 4; j++) acc[i][j] = 0.0f;

#pragma unroll 4
            for (int kk = 0; kk < 512; kk += 32) {
                uint32_t a0 = *(uint32_t*)&As8[(wm4 + gID) * XSTR + kk + tig * 4];
                uint32_t a1 = *(uint32_t*)&As8[(wm4 + gID + 8) * XSTR + kk + tig * 4];
                uint32_t a2 = *(uint32_t*)&As8[(wm4 + gID) * XSTR + kk + 16 + tig * 4];
                uint32_t a3 = *(uint32_t*)&As8[(wm4 + gID + 8) * XSTR + kk + 16 + tig * 4];
#pragma unroll
                for (int nt = 0; nt < 2; nt++) {
                    uint32_t b0 = *(uint32_t*)&Bs8[(wn4 + nt * 8 + gID) * XSTR + kk + tig * 4];
                    uint32_t b1 = *(uint32_t*)&Bs8[(wn4 + nt * 8 + gID) * XSTR + kk + 16 + tig * 4];
                    MMA_E4M3(acc[nt], a0, a1, a2, a3, b0, b1);
                }
            }

            const int r0 = m0 + wm4 + gID, r1 = r0 + 8;
            int tgt0 = text[r0 * NSTEP + s];
            int tgt1 = text[r1 * NSTEP + s];
            const float* e0 = g_Wemb + (size_t)tgt0 * GDIM;
            const float* e1 = g_Wemb + (size_t)tgt1 * GDIM;
            const float sc = 1.0f / 16.0f;
#pragma unroll
            for (int nt = 0; nt < 2; nt++) {
                int cbase = n0 + wn4 + nt * 8 + 2 * tig;
                float2 w0 = *(const float2*)(e0 + cbase);
                float2 w1 = *(const float2*)(e1 + cbase);
                float2 o0 = make_float2(acc[nt][0] * sc + w0.x, acc[nt][1] * sc + w0.y);
                float2 o1 = make_float2(acc[nt][2] * sc + w1.x, acc[nt][3] * sc + w1.y);
                *(float2*)&g_gates[(size_t)r0 * GDIM + cbase] = o0;
                *(float2*)&g_gates[(size_t)r1 * GDIM + cbase] = o1;
            }
        }

        group_sync(grp);   // gates ready within group
    }

    // final LSTM -> hs[25]
    {
        const int r = tid >> 7, jb = tid & 127;
        const int row = b0 + r;
        const int j2 = jb * 2;
        const float* g = g_gates + (size_t)row * GDIM;
        const float* cp = g_c + (size_t)row * HSZ;
        float2 gi = *(const float2*)&g[j2];
        float2 gf = *(const float2*)&g[j2 + 256];
        float2 gg = *(const float2*)&g[j2 + 512];
        float2 go = *(const float2*)&g[j2 + 768];
        float2 co = *(const float2*)&cp[j2];
        float cn0 = fast_sigmoid(gf.x) * co.x + fast_sigmoid(gi.x) * tanh_fast(gg.x);
        float cn1 = fast_sigmoid(gf.y) * co.y + fast_sigmoid(gi.y) * tanh_fast(gg.y);
        float hn0 = fast_sigmoid(go.x) * tanh_fast(cn0);
        float hn1 = fast_sigmoid(go.y) * tanh_fast(cn1);
        *(uint16_t*)(g_hs_f8 + ((size_t)row * NSTEP + (NSTEP - 1)) * HSZ + j2) =
            h2_to_e4m3x2(__floats2half2_rn(hn0, hn1));
    }
}

// ------------------------- launch -------------------------------------------
extern "C" void kernel_launch(void* const* d_in, const int* in_sizes, int n_in,
                              void* d_out, int out_size) {
    const float* batch_H = (const float*)d_in[0];
    const int*   text    = (const int*)d_in[1];
    const float* W_i2h   = (const float*)d_in[3];
    const float* W_h2h   = (const float*)d_in[4];
    const float* b_h2h   = (const float*)d_in[5];
    const float* W_score = (const float*)d_in[6];
    const float* W_ih    = (const float*)d_in[7];
    const float* W_hh    = (const float*)d_in[8];
    const float* b_ih    = (const float*)d_in[9];
    const float* b_hh    = (const float*)d_in[10];
    const float* W_gen   = (const float*)d_in[11];
    const float* b_gen   = (const float*)d_in[12];
    float* out = (float*)d_out;

    uint8_t *Wgen_f8, *hs_f8;
    cudaGetSymbolAddress((void**)&Wgen_f8, g_Wgen_f8);
    cudaGetSymbolAddress((void**)&hs_f8,   g_hs_f8);

    static bool attr_set = false;
    if (!attr_set) {
        cudaFuncSetAttribute(persistent_steps,
                             cudaFuncAttributeMaxDynamicSharedMemorySize,
                             SMEM_BYTES);
        attr_set = true;
    }

    init_kernel<<<2048, 256>>>(W_ih, W_hh, b_ih, b_hh, W_i2h, W_h2h, W_gen);

    persistent_steps<<<NBLK, NTHR, SMEM_BYTES>>>(batch_H, text, b_h2h, W_score);

    qgemm_logits<<<dim3(2, 104), 256>>>(
        hs_f8, Wgen_f8, out, BSZ * NSTEP, NCLS, HSZ, HSZ, HSZ, NCLS, b_gen);
}